// round 3
// baseline (speedup 1.0000x reference)
#include <cuda_runtime.h>
#include <cstddef>

// BilinearMixture: out[e,c] = sum_w (sum_d u[ui,d]*W[w,d]*v[vi,d]) * scalars[w,c]
//                           + u_bias[ui,c] + v_bias[vi,c]
// E=2e6, D=128, NUM_W=3, C=5.
//
// Layout: 16 lanes per edge, 2 edges per warp. Lane l (0..15) owns float4
// indices { i*16 + l : i=0,1 } of the 32-float4 row, so each LDG.128
// instruction covers one contiguous 256B span per edge-group (fully
// coalesced). W held in registers (24/lane, loaded once). No shared memory.
// ~64 regs/thread -> 4 CTAs/SM (vs 2 at 101 regs in the previous round).

#define D 128
#define NUM_W 3
#define NUM_C 5
#define THREADS 256
#define WARPS_PER_BLOCK (THREADS / 32)
#define EDGES_PER_WARP 2
#define EDGES_PER_BLOCK (WARPS_PER_BLOCK * EDGES_PER_WARP)  // 16

__global__ __launch_bounds__(THREADS, 4)
void bilinear_mixture_kernel(
    const float* __restrict__ u_feats,
    const float* __restrict__ v_feats,
    const int*   __restrict__ u_idx,
    const int*   __restrict__ v_idx,
    const float* __restrict__ W,
    const float* __restrict__ scalars,
    const float* __restrict__ u_bias,
    const float* __restrict__ v_bias,
    float*       __restrict__ out,
    int E)
{
    const int tid  = threadIdx.x;
    const int lane = tid & 31;
    const int l    = lane & 15;       // lane within edge-group (0..15)
    const int g    = lane >> 4;       // edge-group within warp (0..1)

    // --- Per-lane constants, loaded once per thread ---
    float4 Wreg[NUM_W][2];
    {
        const float4* Wp = reinterpret_cast<const float4*>(W);
#pragma unroll
        for (int w = 0; w < NUM_W; w++)
#pragma unroll
            for (int i = 0; i < 2; i++)
                Wreg[w][i] = Wp[w * (D / 4) + i * 16 + l];
    }
    float s0 = 0.f, s1 = 0.f, s2 = 0.f;
    if (l < NUM_C) {
        s0 = scalars[0 * NUM_C + l];
        s1 = scalars[1 * NUM_C + l];
        s2 = scalars[2 * NUM_C + l];
    }

    const int warp = tid >> 5;
    const long long e = (long long)blockIdx.x * EDGES_PER_BLOCK
                      + warp * EDGES_PER_WARP + g;
    if (e >= E) return;

    const int ui = u_idx[e];
    const int vi = v_idx[e];

    const float4* up = reinterpret_cast<const float4*>(u_feats) + (size_t)ui * (D / 4);
    const float4* vp = reinterpret_cast<const float4*>(v_feats) + (size_t)vi * (D / 4);

    float4 u4[2], v4[2];
#pragma unroll
    for (int i = 0; i < 2; i++) {
        u4[i] = up[i * 16 + l];
        v4[i] = vp[i * 16 + l];
    }

    float b0 = 0.f, b1 = 0.f, b2 = 0.f;
#pragma unroll
    for (int i = 0; i < 2; i++) {
        const float p0 = u4[i].x * v4[i].x;
        const float p1 = u4[i].y * v4[i].y;
        const float p2 = u4[i].z * v4[i].z;
        const float p3 = u4[i].w * v4[i].w;
        b0 = fmaf(p0, Wreg[0][i].x, fmaf(p1, Wreg[0][i].y,
             fmaf(p2, Wreg[0][i].z, fmaf(p3, Wreg[0][i].w, b0))));
        b1 = fmaf(p0, Wreg[1][i].x, fmaf(p1, Wreg[1][i].y,
             fmaf(p2, Wreg[1][i].z, fmaf(p3, Wreg[1][i].w, b1))));
        b2 = fmaf(p0, Wreg[2][i].x, fmaf(p1, Wreg[2][i].y,
             fmaf(p2, Wreg[2][i].z, fmaf(p3, Wreg[2][i].w, b2))));
    }

    // Butterfly over the 16-lane group: 4 rounds x 3 values.
#pragma unroll
    for (int off = 8; off; off >>= 1) {
        b0 += __shfl_xor_sync(0xffffffffu, b0, off);
        b1 += __shfl_xor_sync(0xffffffffu, b1, off);
        b2 += __shfl_xor_sync(0xffffffffu, b2, off);
    }

    if (l < NUM_C) {
        float o = fmaf(b0, s0, fmaf(b1, s1, b2 * s2));
        o += u_bias[(size_t)ui * NUM_C + l];
        o += v_bias[(size_t)vi * NUM_C + l];
        out[(size_t)e * NUM_C + l] = o;
    }
}

extern "C" void kernel_launch(void* const* d_in, const int* in_sizes, int n_in,
                              void* d_out, int out_size)
{
    const float* u_feats = (const float*)d_in[0];
    const float* v_feats = (const float*)d_in[1];
    const int*   u_idx   = (const int*)  d_in[2];
    const int*   v_idx   = (const int*)  d_in[3];
    const float* W       = (const float*)d_in[4];
    const float* scalars = (const float*)d_in[5];
    const float* u_bias  = (const float*)d_in[6];
    const float* v_bias  = (const float*)d_in[7];
    float* out = (float*)d_out;

    int E = in_sizes[2];  // u_idx element count
    int blocks = (E + EDGES_PER_BLOCK - 1) / EDGES_PER_BLOCK;
    bilinear_mixture_kernel<<<blocks, THREADS>>>(
        u_feats, v_feats, u_idx, v_idx, W, scalars, u_bias, v_bias, out, E);
}

// round 4
// speedup vs baseline: 1.5099x; 1.5099x over previous
#include <cuda_runtime.h>
#include <cstddef>

// BilinearMixture: out[e,c] = sum_w (sum_d u[ui,d]*W[w,d]*v[vi,d]) * scalars[w,c]
//                           + u_bias[ui,c] + v_bias[vi,c]
// E=2e6, D=128, NUM_W=3, C=5.
//
// R2 shape (8 lanes/edge, 4 edges/warp: lane l owns float4 indices i*8+l),
// but W lives in shared (broadcast LDS, 3 wf/edge) instead of 48 registers,
// cutting regs ~101 -> ~60 so 4 CTAs/SM fit (occ ~50% vs 24%).

#define D 128
#define NUM_W 3
#define NUM_C 5
#define THREADS 256
#define WARPS_PER_BLOCK (THREADS / 32)
#define EDGES_PER_WARP 4
#define EDGES_PER_BLOCK (WARPS_PER_BLOCK * EDGES_PER_WARP)  // 32

__global__ __launch_bounds__(THREADS, 4)
void bilinear_mixture_kernel(
    const float* __restrict__ u_feats,
    const float* __restrict__ v_feats,
    const int*   __restrict__ u_idx,
    const int*   __restrict__ v_idx,
    const float* __restrict__ W,
    const float* __restrict__ scalars,
    const float* __restrict__ u_bias,
    const float* __restrict__ v_bias,
    float*       __restrict__ out,
    int E)
{
    __shared__ float4 sW[NUM_W * (D / 4)];   // 3 * 32 float4 = 1.5 KB

    const int tid = threadIdx.x;
    if (tid < NUM_W * (D / 4))
        sW[tid] = reinterpret_cast<const float4*>(W)[tid];
    __syncthreads();

    const int lane = tid & 31;
    const int l    = lane & 7;        // lane within edge-group (0..7)
    const int g    = lane >> 3;       // edge-group within warp (0..3)
    const int warp = tid >> 5;

    const long long e = (long long)blockIdx.x * EDGES_PER_BLOCK
                      + warp * EDGES_PER_WARP + g;
    if (e >= E) return;

    const int ui = u_idx[e];
    const int vi = v_idx[e];

    // Prefetch per-class constants & biases early to overlap with gathers.
    float s0 = 0.f, s1 = 0.f, s2 = 0.f, ub = 0.f, vb = 0.f;
    if (l < NUM_C) {
        s0 = scalars[0 * NUM_C + l];
        s1 = scalars[1 * NUM_C + l];
        s2 = scalars[2 * NUM_C + l];
        ub = u_bias[(size_t)ui * NUM_C + l];
        vb = v_bias[(size_t)vi * NUM_C + l];
    }

    const float4* up = reinterpret_cast<const float4*>(u_feats) + (size_t)ui * (D / 4);
    const float4* vp = reinterpret_cast<const float4*>(v_feats) + (size_t)vi * (D / 4);

    float4 u4[4], v4[4];
#pragma unroll
    for (int i = 0; i < 4; i++) {
        u4[i] = up[i * 8 + l];
        v4[i] = vp[i * 8 + l];
    }

    float b0 = 0.f, b1 = 0.f, b2 = 0.f;
#pragma unroll
    for (int i = 0; i < 4; i++) {
        const float p0 = u4[i].x * v4[i].x;
        const float p1 = u4[i].y * v4[i].y;
        const float p2 = u4[i].z * v4[i].z;
        const float p3 = u4[i].w * v4[i].w;
        // Broadcast LDS: all 4 edge-groups read the same address.
        const float4 w0 = sW[0 * (D / 4) + i * 8 + l];
        const float4 w1 = sW[1 * (D / 4) + i * 8 + l];
        const float4 w2 = sW[2 * (D / 4) + i * 8 + l];
        b0 = fmaf(p0, w0.x, fmaf(p1, w0.y, fmaf(p2, w0.z, fmaf(p3, w0.w, b0))));
        b1 = fmaf(p0, w1.x, fmaf(p1, w1.y, fmaf(p2, w1.z, fmaf(p3, w1.w, b1))));
        b2 = fmaf(p0, w2.x, fmaf(p1, w2.y, fmaf(p2, w2.z, fmaf(p3, w2.w, b2))));
    }

    // Butterfly over the 8-lane group: 3 rounds x 3 values.
#pragma unroll
    for (int off = 4; off; off >>= 1) {
        b0 += __shfl_xor_sync(0xffffffffu, b0, off);
        b1 += __shfl_xor_sync(0xffffffffu, b1, off);
        b2 += __shfl_xor_sync(0xffffffffu, b2, off);
    }

    if (l < NUM_C) {
        float o = fmaf(b0, s0, fmaf(b1, s1, b2 * s2));
        out[(size_t)e * NUM_C + l] = o + ub + vb;
    }
}

extern "C" void kernel_launch(void* const* d_in, const int* in_sizes, int n_in,
                              void* d_out, int out_size)
{
    const float* u_feats = (const float*)d_in[0];
    const float* v_feats = (const float*)d_in[1];
    const int*   u_idx   = (const int*)  d_in[2];
    const int*   v_idx   = (const int*)  d_in[3];
    const float* W       = (const float*)d_in[4];
    const float* scalars = (const float*)d_in[5];
    const float* u_bias  = (const float*)d_in[6];
    const float* v_bias  = (const float*)d_in[7];
    float* out = (float*)d_out;

    int E = in_sizes[2];  // u_idx element count
    int blocks = (E + EDGES_PER_BLOCK - 1) / EDGES_PER_BLOCK;
    bilinear_mixture_kernel<<<blocks, THREADS>>>(
        u_feats, v_feats, u_idx, v_idx, W, scalars, u_bias, v_bias, out, E);
}

// round 5
// speedup vs baseline: 1.6462x; 1.0902x over previous
#include <cuda_runtime.h>
#include <cstddef>

// BilinearMixture: out[e,c] = sum_w (sum_d u[ui,d]*W[w,d]*v[vi,d]) * scalars[w,c]
//                           + u_bias[ui,c] + v_bias[vi,c]
// E=2e6, D=128, NUM_W=3, C=5.
//
// 8 lanes per edge, 4 edge-groups per warp, TWO quads per warp (8 edges).
// All 16 feature LDG.128s issue up front (MLP=16/warp). W is read per
// i-iteration via __ldg broadcast (1 wf, L1-resident 1.5KB) and reused for
// both quads. No shared memory, no syncthreads.

#define D 128
#define NUM_W 3
#define NUM_C 5
#define THREADS 256
#define WARPS_PER_BLOCK (THREADS / 32)
#define EDGES_PER_WARP 8
#define EDGES_PER_BLOCK (WARPS_PER_BLOCK * EDGES_PER_WARP)  // 64

__global__ __launch_bounds__(THREADS, 2)
void bilinear_mixture_kernel(
    const float* __restrict__ u_feats,
    const float* __restrict__ v_feats,
    const int*   __restrict__ u_idx,
    const int*   __restrict__ v_idx,
    const float* __restrict__ W,
    const float* __restrict__ scalars,
    const float* __restrict__ u_bias,
    const float* __restrict__ v_bias,
    float*       __restrict__ out,
    int E)
{
    const int tid  = threadIdx.x;
    const int lane = tid & 31;
    const int l    = lane & 7;        // lane within edge-group (0..7)
    const int g    = lane >> 3;       // edge-group within warp (0..3)
    const int warp = tid >> 5;

    const long long ebase = (long long)blockIdx.x * EDGES_PER_BLOCK
                          + warp * EDGES_PER_WARP;
    const long long e0 = ebase + g;       // quad A edge
    const long long e1 = ebase + 4 + g;   // quad B edge
    const bool val0 = (e0 < E);
    const bool val1 = (e1 < E);

    const int ui0 = val0 ? u_idx[e0] : 0;
    const int vi0 = val0 ? v_idx[e0] : 0;
    const int ui1 = val1 ? u_idx[e1] : 0;
    const int vi1 = val1 ? v_idx[e1] : 0;

    const float4* __restrict__ uf = reinterpret_cast<const float4*>(u_feats);
    const float4* __restrict__ vf = reinterpret_cast<const float4*>(v_feats);
    const float4* up0 = uf + (size_t)ui0 * (D / 4);
    const float4* vp0 = vf + (size_t)vi0 * (D / 4);
    const float4* up1 = uf + (size_t)ui1 * (D / 4);
    const float4* vp1 = vf + (size_t)vi1 * (D / 4);

    // Issue all 16 feature loads up front: MLP = 16 per warp slot.
    float4 ua[4], va[4], ub4[4], vb4[4];
#pragma unroll
    for (int i = 0; i < 4; i++) {
        ua[i]  = __ldg(up0 + i * 8 + l);
        va[i]  = __ldg(vp0 + i * 8 + l);
        ub4[i] = __ldg(up1 + i * 8 + l);
        vb4[i] = __ldg(vp1 + i * 8 + l);
    }

    // Per-class constants + bias gathers (overlap with outstanding loads).
    float s0 = 0.f, s1 = 0.f, s2 = 0.f;
    float ubias0 = 0.f, vbias0 = 0.f, ubias1 = 0.f, vbias1 = 0.f;
    if (l < NUM_C) {
        s0 = __ldg(scalars + 0 * NUM_C + l);
        s1 = __ldg(scalars + 1 * NUM_C + l);
        s2 = __ldg(scalars + 2 * NUM_C + l);
        ubias0 = __ldg(u_bias + (size_t)ui0 * NUM_C + l);
        vbias0 = __ldg(v_bias + (size_t)vi0 * NUM_C + l);
        ubias1 = __ldg(u_bias + (size_t)ui1 * NUM_C + l);
        vbias1 = __ldg(v_bias + (size_t)vi1 * NUM_C + l);
    }

    const float4* __restrict__ Wp = reinterpret_cast<const float4*>(W);

    float a0 = 0.f, a1 = 0.f, a2 = 0.f;   // quad A bases
    float c0 = 0.f, c1 = 0.f, c2 = 0.f;   // quad B bases
#pragma unroll
    for (int i = 0; i < 4; i++) {
        // Broadcast W loads (1 wf each, L1-hit), reused by both quads.
        const float4 w0 = __ldg(Wp + 0 * (D / 4) + i * 8 + l);
        const float4 w1 = __ldg(Wp + 1 * (D / 4) + i * 8 + l);
        const float4 w2 = __ldg(Wp + 2 * (D / 4) + i * 8 + l);

        {
            const float p0 = ua[i].x * va[i].x;
            const float p1 = ua[i].y * va[i].y;
            const float p2 = ua[i].z * va[i].z;
            const float p3 = ua[i].w * va[i].w;
            a0 = fmaf(p0, w0.x, fmaf(p1, w0.y, fmaf(p2, w0.z, fmaf(p3, w0.w, a0))));
            a1 = fmaf(p0, w1.x, fmaf(p1, w1.y, fmaf(p2, w1.z, fmaf(p3, w1.w, a1))));
            a2 = fmaf(p0, w2.x, fmaf(p1, w2.y, fmaf(p2, w2.z, fmaf(p3, w2.w, a2))));
        }
        {
            const float p0 = ub4[i].x * vb4[i].x;
            const float p1 = ub4[i].y * vb4[i].y;
            const float p2 = ub4[i].z * vb4[i].z;
            const float p3 = ub4[i].w * vb4[i].w;
            c0 = fmaf(p0, w0.x, fmaf(p1, w0.y, fmaf(p2, w0.z, fmaf(p3, w0.w, c0))));
            c1 = fmaf(p0, w1.x, fmaf(p1, w1.y, fmaf(p2, w1.z, fmaf(p3, w1.w, c1))));
            c2 = fmaf(p0, w2.x, fmaf(p1, w2.y, fmaf(p2, w2.z, fmaf(p3, w2.w, c2))));
        }
    }

    // Butterfly over the 8-lane group: 3 rounds x 6 values (2 quads).
#pragma unroll
    for (int off = 4; off; off >>= 1) {
        a0 += __shfl_xor_sync(0xffffffffu, a0, off);
        a1 += __shfl_xor_sync(0xffffffffu, a1, off);
        a2 += __shfl_xor_sync(0xffffffffu, a2, off);
        c0 += __shfl_xor_sync(0xffffffffu, c0, off);
        c1 += __shfl_xor_sync(0xffffffffu, c1, off);
        c2 += __shfl_xor_sync(0xffffffffu, c2, off);
    }

    if (l < NUM_C) {
        if (val0) {
            float o = fmaf(a0, s0, fmaf(a1, s1, a2 * s2));
            out[(size_t)e0 * NUM_C + l] = o + ubias0 + vbias0;
        }
        if (val1) {
            float o = fmaf(c0, s0, fmaf(c1, s1, c2 * s2));
            out[(size_t)e1 * NUM_C + l] = o + ubias1 + vbias1;
        }
    }
}

extern "C" void kernel_launch(void* const* d_in, const int* in_sizes, int n_in,
                              void* d_out, int out_size)
{
    const float* u_feats = (const float*)d_in[0];
    const float* v_feats = (const float*)d_in[1];
    const int*   u_idx   = (const int*)  d_in[2];
    const int*   v_idx   = (const int*)  d_in[3];
    const float* W       = (const float*)d_in[4];
    const float* scalars = (const float*)d_in[5];
    const float* u_bias  = (const float*)d_in[6];
    const float* v_bias  = (const float*)d_in[7];
    float* out = (float*)d_out;

    int E = in_sizes[2];  // u_idx element count
    int blocks = (E + EDGES_PER_BLOCK - 1) / EDGES_PER_BLOCK;
    bilinear_mixture_kernel<<<blocks, THREADS>>>(
        u_feats, v_feats, u_idx, v_idx, W, scalars, u_bias, v_bias, out, E);
}